// round 1
// baseline (speedup 1.0000x reference)
#include <cuda_runtime.h>
#include <math.h>

#define NELEM 16384
#define SCORE_LIMIT 8192
#define NT 1024
#define EPT 16   // elements per thread (NELEM / NT)

__global__ __launch_bounds__(NT, 1)
void connect_attention_fused(const float* __restrict__ x,
                             const float* __restrict__ w7,
                             float* __restrict__ out)
{
    extern __shared__ unsigned char smem_raw[];
    float*        sx     = (float*)smem_raw;                 // NELEM floats
    unsigned int* sb     = (unsigned int*)(sx + NELEM);      // NELEM score bit patterns
    unsigned int* hist   = (unsigned int*)(sb + NELEM);      // 256 bins
    unsigned int* eqmask = hist + 256;                       // 512 words (NELEM/32)

    __shared__ unsigned int s_prefix, s_remk;
    __shared__ float sw[8];

    const int tid = threadIdx.x;

    if (tid < 7) sw[tid] = w7[tid];

    // ---- load x (coalesced, striped) ----
    #pragma unroll
    for (int r = 0; r < EPT; ++r)
        sx[tid + r * NT] = x[tid + r * NT];
    __syncthreads();

    const float w0 = sw[0], w1 = sw[1], w2 = sw[2], w3 = sw[3],
                w4 = sw[4], w5 = sw[5], w6 = sw[6];

    // ---- conv 'same' (y[n] = sum_j x[n+j-3]*w[j]) + sigmoid ----
    #pragma unroll
    for (int r = 0; r < EPT; ++r) {
        int i = tid + r * NT;
        float y = 0.0f;
        #pragma unroll
        for (int j = 0; j < 7; ++j) {
            int k = i + j - 3;
            float xv = (k >= 0 && k < NELEM) ? sx[k] : 0.0f;
            float wj = (j == 0) ? w0 : (j == 1) ? w1 : (j == 2) ? w2 :
                       (j == 3) ? w3 : (j == 4) ? w4 : (j == 5) ? w5 : w6;
            y = fmaf(xv, wj, y);
        }
        float s = 1.0f / (1.0f + expf(-y));
        sb[i] = __float_as_uint(s);     // positive floats: bit order == value order
    }
    __syncthreads();

    // ---- 4-pass radix select: find rank-8192 threshold under stable ordering ----
    unsigned int prefix = 0;        // value of selected high bits so far
    unsigned int remk   = SCORE_LIMIT;

    for (int pass = 0; pass < 4; ++pass) {
        const int shift = 24 - 8 * pass;

        if (tid < 256) hist[tid] = 0;
        __syncthreads();

        #pragma unroll
        for (int r = 0; r < EPT; ++r) {
            unsigned int b = sb[tid + r * NT];
            bool cand = (pass == 0) || ((b >> (shift + 8)) == prefix);
            if (cand) atomicAdd(&hist[(b >> shift) & 255u], 1u);
        }
        __syncthreads();

        // warp 0: find the bin containing rank 'remk'
        if (tid < 32) {
            unsigned int lh[8];
            unsigned int lsum = 0;
            #pragma unroll
            for (int q = 0; q < 8; ++q) { lh[q] = hist[tid * 8 + q]; lsum += lh[q]; }
            // inclusive scan across lanes
            unsigned int inc = lsum;
            #pragma unroll
            for (int o = 1; o < 32; o <<= 1) {
                unsigned int v = __shfl_up_sync(0xffffffffu, inc, o);
                if (tid >= o) inc += v;
            }
            unsigned int excl = inc - lsum;
            if (excl < remk && remk <= inc) {   // exactly one lane
                unsigned int cum = excl;
                int bin = tid * 8;
                #pragma unroll
                for (int q = 0; q < 8; ++q) {
                    if (cum + lh[q] >= remk) { bin = tid * 8 + q; break; }
                    cum += lh[q];
                }
                s_prefix = (prefix << 8) | (unsigned int)bin;
                s_remk   = remk - cum;
            }
        }
        __syncthreads();
        prefix = s_prefix;
        remk   = s_remk;
        // next pass's hist-zero + sync separates this read from the next write
    }

    const unsigned int T = prefix;   // exact score bits at the boundary
    // remk = number of elements equal to T that are kept (smallest indices first)

    // ---- tie bitmask ----
    if (tid < 512) eqmask[tid] = 0;
    __syncthreads();
    #pragma unroll
    for (int r = 0; r < EPT; ++r) {
        int i = tid + r * NT;
        if (sb[i] == T) atomicOr(&eqmask[i >> 5], 1u << (i & 31));
    }
    __syncthreads();

    // ---- emit outputs ----
    #pragma unroll
    for (int r = 0; r < EPT; ++r) {
        int i = tid + r * NT;
        unsigned int b = sb[i];
        float s = __uint_as_float(b);
        bool keep;
        if (b < T)      keep = true;
        else if (b > T) keep = false;
        else {
            // stable tie-break: rank among equals by ascending index
            unsigned int rank = 0;
            int wrd = i >> 5;
            for (int q = 0; q < wrd; ++q) rank += __popc(eqmask[q]);
            rank += __popc(eqmask[wrd] & ((1u << (i & 31)) - 1u));
            keep = (rank < remk);
        }
        out[i]         = keep ? sx[i] * (s + 1.0f) : 0.0f;
        out[NELEM + i] = s;
    }
}

extern "C" void kernel_launch(void* const* d_in, const int* in_sizes, int n_in,
                              void* d_out, int out_size)
{
    const float* x = (const float*)d_in[0];
    const float* w = (const float*)d_in[1];
    // defensive: metadata order should be (x[16384], conv_w[7])
    if (n_in >= 2 && in_sizes[0] == 7) {
        const float* t = x; x = w; w = t;
    }
    float* out = (float*)d_out;

    size_t smem = (size_t)NELEM * 4 * 2 + 256 * 4 + 512 * 4;   // 134144 B
    cudaFuncSetAttribute(connect_attention_fused,
                         cudaFuncAttributeMaxDynamicSharedMemorySize, (int)smem);
    connect_attention_fused<<<1, NT, smem>>>(x, w, out);
}